// round 5
// baseline (speedup 1.0000x reference)
#include <cuda_runtime.h>
#include <stdint.h>

// Problem constants
#define BB 16
#define NN 4096
#define DD 256
#define KK 512
#define MM (BB * NN)            // 65536 positions
#define COMMIT_W 0.25f
#define MARGIN 1.25f            // > 2x worst-case tf32 screen error per distance pair

// Scratch (device globals: no allocation allowed)
__device__ float         g_esq[KK];
__device__ int           g_best[MM];
__device__ unsigned char g_flag[MM];
__device__ double        g_loss;

// ---------------------------------------------------------------------------
// helpers
// ---------------------------------------------------------------------------
__device__ __forceinline__ float to_tf32(float x) {
    unsigned u;
    asm("cvt.rna.tf32.f32 %0, %1;" : "=r"(u) : "f"(x));
    return __uint_as_float(u);
}

__device__ __forceinline__ void mma_tf32(float d[4], const unsigned a[4], const unsigned b[2]) {
    asm volatile(
        "mma.sync.aligned.m16n8k8.row.col.f32.tf32.tf32.f32 "
        "{%0,%1,%2,%3}, {%4,%5,%6,%7}, {%8,%9}, {%0,%1,%2,%3};\n"
        : "+f"(d[0]), "+f"(d[1]), "+f"(d[2]), "+f"(d[3])
        : "r"(a[0]), "r"(a[1]), "r"(a[2]), "r"(a[3]), "r"(b[0]), "r"(b[1]));
}

// ---------------------------------------------------------------------------
// Kernel 0: precompute ||e_k||^2 (fp32 exact) and zero the loss accumulator.
// ---------------------------------------------------------------------------
__global__ void prep_kernel(const float* __restrict__ cb) {
    int k = blockIdx.x * blockDim.x + threadIdx.x;
    if (k == 0) g_loss = 0.0;
    if (k < KK) {
        const float4* row = (const float4*)(cb + (size_t)k * DD);
        float s = 0.f;
#pragma unroll 16
        for (int i = 0; i < DD / 4; i++) {
            float4 v = row[i];
            s += v.x * v.x + v.y * v.y + v.z * v.z + v.w * v.w;
        }
        g_esq[k] = s;
    }
}

// ---------------------------------------------------------------------------
// Kernel 1: TF32 tensor-core screen with top-2 tracking.
// CTA: 256 thr (8 warps, 4x2 grid). CTA tile: 128 rows x 128 codes per pass,
// 4 passes cover K=512. Warp tile 32x64: 2 m16 tiles x 8 n8 tiles = 16 MMAs.
// Smem stride 20 floats (4*odd): all fragment LDS are 32-bank conflict-free.
// ---------------------------------------------------------------------------
__global__ void __launch_bounds__(256, 2) screen_kernel(
    const float* __restrict__ z, const float* __restrict__ cb)
{
    __shared__ float zs[128][20];   // [row][d]  (tf32-rounded)
    __shared__ float cs[128][20];   // [code][d] (tf32-rounded)
    __shared__ float rv1[128][8];
    __shared__ float rv2[128][8];
    __shared__ int   ri1[128][8];

    const int tid  = threadIdx.x;
    const int warp = tid >> 5;
    const int lane = tid & 31;
    const int wm   = warp >> 1;        // 0..3
    const int wn   = warp & 1;         // 0..1
    const int g    = lane >> 2;        // 0..7
    const int tig  = lane & 3;         // 0..3
    const int row0 = blockIdx.x * 128;

    // per-thread top-2 for 4 rows: e = mt*2 + h, row = wm*32 + mt*16 + g + 8h
    float v1[4], v2[4];
    int   i1[4];
#pragma unroll
    for (int e = 0; e < 4; e++) { v1[e] = 3.4e38f; v2[e] = 3.4e38f; i1[e] = 0; }

    for (int kc = 0; kc < KK / 128; kc++) {
        float acc[2][8][4];
#pragma unroll
        for (int mt = 0; mt < 2; mt++)
#pragma unroll
            for (int nt = 0; nt < 8; nt++)
#pragma unroll
                for (int c = 0; c < 4; c++) acc[mt][nt][c] = 0.f;

        for (int dc = 0; dc < DD; dc += 16) {
            __syncthreads();
            // load tiles (tf32-rounded). 512 float4 each; 2 per thread.
#pragma unroll
            for (int s = 0; s < 2; s++) {
                int i  = tid + s * 256;
                int r  = i >> 2;
                int c4 = i & 3;
                float4 zv = *(const float4*)(z + (size_t)(row0 + r) * DD + dc + c4 * 4);
                zv.x = to_tf32(zv.x); zv.y = to_tf32(zv.y);
                zv.z = to_tf32(zv.z); zv.w = to_tf32(zv.w);
                *(float4*)&zs[r][c4 * 4] = zv;
                float4 cv = *(const float4*)(cb + (size_t)(kc * 128 + r) * DD + dc + c4 * 4);
                cv.x = to_tf32(cv.x); cv.y = to_tf32(cv.y);
                cv.z = to_tf32(cv.z); cv.w = to_tf32(cv.w);
                *(float4*)&cs[r][c4 * 4] = cv;
            }
            __syncthreads();

#pragma unroll
            for (int q = 0; q < 2; q++) {
                const int q8 = q * 8;
                unsigned afr[2][4];
#pragma unroll
                for (int mt = 0; mt < 2; mt++) {
                    int rb = wm * 32 + mt * 16;
                    afr[mt][0] = __float_as_uint(zs[rb + g    ][q8 + tig    ]);
                    afr[mt][1] = __float_as_uint(zs[rb + g + 8][q8 + tig    ]);
                    afr[mt][2] = __float_as_uint(zs[rb + g    ][q8 + tig + 4]);
                    afr[mt][3] = __float_as_uint(zs[rb + g + 8][q8 + tig + 4]);
                }
                unsigned bfr[8][2];
#pragma unroll
                for (int nt = 0; nt < 8; nt++) {
                    int nb = wn * 64 + nt * 8 + g;
                    bfr[nt][0] = __float_as_uint(cs[nb][q8 + tig    ]);
                    bfr[nt][1] = __float_as_uint(cs[nb][q8 + tig + 4]);
                }
#pragma unroll
                for (int mt = 0; mt < 2; mt++)
#pragma unroll
                    for (int nt = 0; nt < 8; nt++)
                        mma_tf32(acc[mt][nt], afr[mt], bfr[nt]);
            }
        }

        // fold this pass's 128 codes into top-2 (k ascending => first-hit ties)
#pragma unroll
        for (int nt = 0; nt < 8; nt++) {
#pragma unroll
            for (int c = 0; c < 4; c++) {
                int k = kc * 128 + wn * 64 + nt * 8 + 2 * tig + (c & 1);
                float es = g_esq[k];
#pragma unroll
                for (int mt = 0; mt < 2; mt++) {
                    int e = mt * 2 + (c >> 1);
                    float dist = fmaf(-2.f, acc[mt][nt][c], es);
                    if (dist < v1[e]) { v2[e] = v1[e]; v1[e] = dist; i1[e] = k; }
                    else if (dist < v2[e]) { v2[e] = dist; }
                }
            }
        }
    }

    // cross-thread reduction: 8 threads per row (slot = wn*4 + tig)
    __syncthreads();
    const int slot = wn * 4 + tig;
#pragma unroll
    for (int e = 0; e < 4; e++) {
        int r = wm * 32 + (e >> 1) * 16 + g + 8 * (e & 1);
        rv1[r][slot] = v1[e];
        ri1[r][slot] = i1[e];
        rv2[r][slot] = v2[e];
    }
    __syncthreads();
    if (tid < 128) {
        float V1 = rv1[tid][0], V2 = rv2[tid][0];
        int   I1 = ri1[tid][0];
#pragma unroll
        for (int s = 1; s < 8; s++) {
            float a = rv1[tid][s], b = rv2[tid][s];
            int  ia = ri1[tid][s];
            if (a < V1)       { V2 = fminf(V1, b); V1 = a; I1 = ia; }
            else if (a == V1) { if (ia < I1) I1 = ia; V2 = V1; }   // tie -> rescore
            else              { V2 = fminf(V2, a); }
        }
        g_best[row0 + tid] = I1;
        g_flag[row0 + tid] = (V2 - V1 <= MARGIN) ? 1 : 0;
    }
}

// ---------------------------------------------------------------------------
// Kernel 2: exact fp32 rescore of flagged rows. One warp per row; warps on
// unflagged rows exit immediately (no __syncthreads in this kernel).
// ---------------------------------------------------------------------------
__global__ void __launch_bounds__(256) rescore_kernel(
    const float* __restrict__ z, const float* __restrict__ cb)
{
    const int warp = threadIdx.x >> 5;
    const int lane = threadIdx.x & 31;
    const int pos  = blockIdx.x * 8 + warp;
    if (!g_flag[pos]) return;

    // each lane owns an 8-float d-slice of z
    float4 za = *(const float4*)(z + (size_t)pos * DD + lane * 8);
    float4 zb = *(const float4*)(z + (size_t)pos * DD + lane * 8 + 4);

    float bestv = 3.4e38f;
    int   besti = 0;
    for (int k0 = 0; k0 < KK; k0 += 2) {
        float s0, s1;
        {
            const float* e = cb + (size_t)k0 * DD + lane * 8;
            float4 ea = *(const float4*)e;
            float4 eb = *(const float4*)(e + 4);
            s0 = za.x * ea.x + za.y * ea.y + za.z * ea.z + za.w * ea.w
               + zb.x * eb.x + zb.y * eb.y + zb.z * eb.z + zb.w * eb.w;
        }
        {
            const float* e = cb + (size_t)(k0 + 1) * DD + lane * 8;
            float4 ea = *(const float4*)e;
            float4 eb = *(const float4*)(e + 4);
            s1 = za.x * ea.x + za.y * ea.y + za.z * ea.z + za.w * ea.w
               + zb.x * eb.x + zb.y * eb.y + zb.z * eb.z + zb.w * eb.w;
        }
#pragma unroll
        for (int off = 16; off > 0; off >>= 1) {
            s0 += __shfl_down_sync(0xFFFFFFFFu, s0, off);
            s1 += __shfl_down_sync(0xFFFFFFFFu, s1, off);
        }
        if (lane == 0) {
            float d0 = fmaf(-2.f, s0, g_esq[k0]);
            float d1 = fmaf(-2.f, s1, g_esq[k0 + 1]);
            if (d0 < bestv) { bestv = d0; besti = k0; }
            if (d1 < bestv) { bestv = d1; besti = k0 + 1; }
        }
    }
    if (lane == 0) g_best[pos] = besti;
}

// ---------------------------------------------------------------------------
// Kernel 3: gather + mask + loss accumulation. One warp per position.
// Mask read as 32-bit words (nonzero == true): works for int32 or float32.
// ---------------------------------------------------------------------------
__global__ void __launch_bounds__(256) quant_kernel(
    const float* __restrict__ z, const unsigned int* __restrict__ mask,
    const float* __restrict__ cb, float* __restrict__ outq,
    float* __restrict__ outi)
{
    __shared__ float wsum[8];
    const int warp = threadIdx.x >> 5;
    const int lane = threadIdx.x & 31;
    const int pos  = blockIdx.x * 8 + warp;

    const int idx = g_best[pos];
    const bool mk = (mask[pos] != 0u);
    const float m = mk ? 1.f : 0.f;
    const float4* zp = (const float4*)(z  + (size_t)pos * DD);
    const float4* ep = (const float4*)(cb + (size_t)idx * DD);
    float4* op = (float4*)(outq + (size_t)pos * DD);

    float s = 0.f;
#pragma unroll
    for (int i = lane; i < DD / 4; i += 32) {
        float4 zv = zp[i];
        float4 ev = ep[i];
        float dx = ev.x - zv.x, dy = ev.y - zv.y,
              dz = ev.z - zv.z, dw = ev.w - zv.w;
        s += dx * dx + dy * dy + dz * dz + dw * dw;
        op[i] = make_float4(ev.x * m, ev.y * m, ev.z * m, ev.w * m);
    }
    if (lane == 0) outi[pos] = mk ? (float)idx : -1.0f;

#pragma unroll
    for (int off = 16; off > 0; off >>= 1)
        s += __shfl_down_sync(0xFFFFFFFFu, s, off);
    if (lane == 0) wsum[warp] = s;
    __syncthreads();
    if (threadIdx.x == 0) {
        float b = 0.f;
#pragma unroll
        for (int w = 0; w < 8; w++) b += wsum[w];
        atomicAdd(&g_loss, (double)b);
    }
}

// ---------------------------------------------------------------------------
// Kernel 4: finalize commit loss.
// ---------------------------------------------------------------------------
__global__ void finalize_kernel(float* __restrict__ out_loss) {
    out_loss[0] = (float)(COMMIT_W * g_loss / ((double)MM * (double)DD));
}

// ---------------------------------------------------------------------------
extern "C" void kernel_launch(void* const* d_in, const int* in_sizes, int n_in,
                              void* d_out, int out_size) {
    const float*        z    = (const float*)d_in[0];
    const unsigned int* mask = (const unsigned int*)d_in[1];
    const float*        cb   = (const float*)d_in[2];

    float* outq = (float*)d_out;                         // (B,N,D)
    float* outi = outq + (size_t)MM * DD;                // (B,N) indices as float
    float* outl = outi + MM;                             // scalar loss

    prep_kernel<<<1, 512>>>(cb);
    screen_kernel<<<MM / 128, 256>>>(z, cb);
    rescore_kernel<<<MM / 8, 256>>>(z, cb);
    quant_kernel<<<MM / 8, 256>>>(z, mask, cb, outq, outi);
    finalize_kernel<<<1, 1>>>(outl);
}

// round 6
// speedup vs baseline: 2.1157x; 2.1157x over previous
#include <cuda_runtime.h>
#include <stdint.h>

// Problem constants
#define BB 16
#define NN 4096
#define DD 256
#define KK 512
#define MM (BB * NN)            // 65536 positions
#define COMMIT_W 0.25f
#define MARGIN 1.25f            // > 2x worst-case tf32 screen error per distance pair

// Scratch (device globals: no allocation allowed)
__device__ float         g_esq[KK];
__device__ int           g_best[MM];
__device__ int           g_list[MM];
__device__ int           g_count;
__device__ double        g_loss;

// ---------------------------------------------------------------------------
// helpers
// ---------------------------------------------------------------------------
__device__ __forceinline__ float to_tf32(float x) {
    unsigned u;
    asm("cvt.rna.tf32.f32 %0, %1;" : "=r"(u) : "f"(x));
    return __uint_as_float(u);
}

__device__ __forceinline__ void mma_tf32(float d[4], const unsigned a[4], const unsigned b[2]) {
    asm volatile(
        "mma.sync.aligned.m16n8k8.row.col.f32.tf32.tf32.f32 "
        "{%0,%1,%2,%3}, {%4,%5,%6,%7}, {%8,%9}, {%0,%1,%2,%3};\n"
        : "+f"(d[0]), "+f"(d[1]), "+f"(d[2]), "+f"(d[3])
        : "r"(a[0]), "r"(a[1]), "r"(a[2]), "r"(a[3]), "r"(b[0]), "r"(b[1]));
}

// ---------------------------------------------------------------------------
// Kernel 0: precompute ||e_k||^2 (fp32 exact); zero loss + compaction count.
// ---------------------------------------------------------------------------
__global__ void prep_kernel(const float* __restrict__ cb) {
    int k = blockIdx.x * blockDim.x + threadIdx.x;
    if (k == 0) { g_loss = 0.0; g_count = 0; }
    if (k < KK) {
        const float4* row = (const float4*)(cb + (size_t)k * DD);
        float s = 0.f;
#pragma unroll 16
        for (int i = 0; i < DD / 4; i++) {
            float4 v = row[i];
            s += v.x * v.x + v.y * v.y + v.z * v.z + v.w * v.w;
        }
        g_esq[k] = s;
    }
}

// ---------------------------------------------------------------------------
// Kernel 1: TF32 tensor-core screen with top-2 tracking.
// CTA: 256 thr (8 warps, 4x2 grid). CTA tile: 128 rows x 128 codes per pass,
// 4 passes cover K=512. Warp tile 32x64: 2 m16 tiles x 8 n8 tiles = 16 MMAs.
// Rows whose top-2 gap <= MARGIN get appended to g_list for exact rescore.
// ---------------------------------------------------------------------------
__global__ void __launch_bounds__(256, 2) screen_kernel(
    const float* __restrict__ z, const float* __restrict__ cb)
{
    __shared__ float zs[128][20];   // [row][d]  (tf32-rounded)
    __shared__ float cs[128][20];   // [code][d] (tf32-rounded)
    __shared__ float rv1[128][8];
    __shared__ float rv2[128][8];
    __shared__ int   ri1[128][8];

    const int tid  = threadIdx.x;
    const int warp = tid >> 5;
    const int lane = tid & 31;
    const int wm   = warp >> 1;        // 0..3
    const int wn   = warp & 1;         // 0..1
    const int g    = lane >> 2;        // 0..7
    const int tig  = lane & 3;         // 0..3
    const int row0 = blockIdx.x * 128;

    // per-thread top-2 for 4 rows: e = mt*2 + h, row = wm*32 + mt*16 + g + 8h
    float v1[4], v2[4];
    int   i1[4];
#pragma unroll
    for (int e = 0; e < 4; e++) { v1[e] = 3.4e38f; v2[e] = 3.4e38f; i1[e] = 0; }

    for (int kc = 0; kc < KK / 128; kc++) {
        float acc[2][8][4];
#pragma unroll
        for (int mt = 0; mt < 2; mt++)
#pragma unroll
            for (int nt = 0; nt < 8; nt++)
#pragma unroll
                for (int c = 0; c < 4; c++) acc[mt][nt][c] = 0.f;

        for (int dc = 0; dc < DD; dc += 16) {
            __syncthreads();
            // load tiles (tf32-rounded). 512 float4 each; 2 per thread.
#pragma unroll
            for (int s = 0; s < 2; s++) {
                int i  = tid + s * 256;
                int r  = i >> 2;
                int c4 = i & 3;
                float4 zv = *(const float4*)(z + (size_t)(row0 + r) * DD + dc + c4 * 4);
                zv.x = to_tf32(zv.x); zv.y = to_tf32(zv.y);
                zv.z = to_tf32(zv.z); zv.w = to_tf32(zv.w);
                *(float4*)&zs[r][c4 * 4] = zv;
                float4 cv = *(const float4*)(cb + (size_t)(kc * 128 + r) * DD + dc + c4 * 4);
                cv.x = to_tf32(cv.x); cv.y = to_tf32(cv.y);
                cv.z = to_tf32(cv.z); cv.w = to_tf32(cv.w);
                *(float4*)&cs[r][c4 * 4] = cv;
            }
            __syncthreads();

#pragma unroll
            for (int q = 0; q < 2; q++) {
                const int q8 = q * 8;
                unsigned afr[2][4];
#pragma unroll
                for (int mt = 0; mt < 2; mt++) {
                    int rb = wm * 32 + mt * 16;
                    afr[mt][0] = __float_as_uint(zs[rb + g    ][q8 + tig    ]);
                    afr[mt][1] = __float_as_uint(zs[rb + g + 8][q8 + tig    ]);
                    afr[mt][2] = __float_as_uint(zs[rb + g    ][q8 + tig + 4]);
                    afr[mt][3] = __float_as_uint(zs[rb + g + 8][q8 + tig + 4]);
                }
                unsigned bfr[8][2];
#pragma unroll
                for (int nt = 0; nt < 8; nt++) {
                    int nb = wn * 64 + nt * 8 + g;
                    bfr[nt][0] = __float_as_uint(cs[nb][q8 + tig    ]);
                    bfr[nt][1] = __float_as_uint(cs[nb][q8 + tig + 4]);
                }
#pragma unroll
                for (int mt = 0; mt < 2; mt++)
#pragma unroll
                    for (int nt = 0; nt < 8; nt++)
                        mma_tf32(acc[mt][nt], afr[mt], bfr[nt]);
            }
        }

        // fold this pass's 128 codes into top-2 (k ascending => first-hit ties)
#pragma unroll
        for (int nt = 0; nt < 8; nt++) {
#pragma unroll
            for (int c = 0; c < 4; c++) {
                int k = kc * 128 + wn * 64 + nt * 8 + 2 * tig + (c & 1);
                float es = g_esq[k];
#pragma unroll
                for (int mt = 0; mt < 2; mt++) {
                    int e = mt * 2 + (c >> 1);
                    float dist = fmaf(-2.f, acc[mt][nt][c], es);
                    if (dist < v1[e]) { v2[e] = v1[e]; v1[e] = dist; i1[e] = k; }
                    else if (dist < v2[e]) { v2[e] = dist; }
                }
            }
        }
    }

    // cross-thread reduction: 8 threads per row (slot = wn*4 + tig)
    __syncthreads();
    const int slot = wn * 4 + tig;
#pragma unroll
    for (int e = 0; e < 4; e++) {
        int r = wm * 32 + (e >> 1) * 16 + g + 8 * (e & 1);
        rv1[r][slot] = v1[e];
        ri1[r][slot] = i1[e];
        rv2[r][slot] = v2[e];
    }
    __syncthreads();
    if (tid < 128) {
        float V1 = rv1[tid][0], V2 = rv2[tid][0];
        int   I1 = ri1[tid][0];
#pragma unroll
        for (int s = 1; s < 8; s++) {
            float a = rv1[tid][s], b = rv2[tid][s];
            int  ia = ri1[tid][s];
            if (a < V1)       { V2 = fminf(V1, b); V1 = a; I1 = ia; }
            else if (a == V1) { if (ia < I1) I1 = ia; V2 = V1; }   // tie -> rescore
            else              { V2 = fminf(V2, a); }
        }
        g_best[row0 + tid] = I1;
        if (V2 - V1 <= MARGIN) {
            int p = atomicAdd(&g_count, 1);
            g_list[p] = row0 + tid;
        }
    }
}

// ---------------------------------------------------------------------------
// Kernel 2: exact fp32 rescore of compacted flagged rows, tiled GEMM-argmin.
// CTA: 256 thr (tm 0..15, tk 0..15), 64 gathered rows x all 512 codes, 4x4
// register fragments, codebook staged through smem (read ~O(count/64) times
// total instead of once per flagged row). Grid covers worst case; CTAs past
// the live count exit uniformly. Partial tiles pad with the last valid row
// (duplicate writes carry identical values -> deterministic).
// ---------------------------------------------------------------------------
__global__ void __launch_bounds__(256, 2) rescore_kernel(
    const float* __restrict__ z, const float* __restrict__ cb)
{
    const int cnt = g_count;
    if (blockIdx.x * 64 >= cnt) return;

    __shared__ int   rowid[64];
    __shared__ float zs[64][64];   // [d][m]
    __shared__ float cs[64][64];   // [d][k]
    __shared__ float redv[64][17];
    __shared__ int   redi[64][17];

    const int tid = threadIdx.x;
    const int tm  = tid & 15;
    const int tk  = tid >> 4;

    if (tid < 64) {
        int i = blockIdx.x * 64 + tid;
        rowid[tid] = g_list[i < cnt ? i : cnt - 1];
    }
    __syncthreads();

    const int lm = tid & 63;
    const int lq = tid >> 6;       // 0..3
    const int myrow = rowid[lm];

    float bestv[4];
    int   besti[4];
#pragma unroll
    for (int i = 0; i < 4; i++) { bestv[i] = 3.4e38f; besti[i] = 0; }

    for (int kc = 0; kc < KK; kc += 64) {
        float acc[4][4];
#pragma unroll
        for (int i = 0; i < 4; i++)
#pragma unroll
            for (int j = 0; j < 4; j++) acc[i][j] = 0.f;

        for (int dc = 0; dc < DD; dc += 64) {
            __syncthreads();
            {
                const float4* zp = (const float4*)(z + (size_t)myrow * DD + dc + lq * 16);
#pragma unroll
                for (int i = 0; i < 4; i++) {
                    float4 v = zp[i];
                    int d = lq * 16 + i * 4;
                    zs[d + 0][lm] = v.x; zs[d + 1][lm] = v.y;
                    zs[d + 2][lm] = v.z; zs[d + 3][lm] = v.w;
                }
            }
            {
                const float4* cp = (const float4*)(cb + (size_t)(kc + lm) * DD + dc + lq * 16);
#pragma unroll
                for (int i = 0; i < 4; i++) {
                    float4 v = cp[i];
                    int d = lq * 16 + i * 4;
                    cs[d + 0][lm] = v.x; cs[d + 1][lm] = v.y;
                    cs[d + 2][lm] = v.z; cs[d + 3][lm] = v.w;
                }
            }
            __syncthreads();

#pragma unroll 16
            for (int d = 0; d < 64; d++) {
                float4 za = *(const float4*)&zs[d][tm * 4];
                float4 ca = *(const float4*)&cs[d][tk * 4];
                float zr[4] = { za.x, za.y, za.z, za.w };
                float cr[4] = { ca.x, ca.y, ca.z, ca.w };
#pragma unroll
                for (int i = 0; i < 4; i++)
#pragma unroll
                    for (int j = 0; j < 4; j++)
                        acc[i][j] += zr[i] * cr[j];
            }
        }

        // fold (indices ascending; strict < keeps first hit, matching argmin)
#pragma unroll
        for (int j = 0; j < 4; j++) {
            int kidx = kc + tk * 4 + j;
            float es = g_esq[kidx];
#pragma unroll
            for (int i = 0; i < 4; i++) {
                float dist = fmaf(-2.f, acc[i][j], es);
                if (dist < bestv[i]) { bestv[i] = dist; besti[i] = kidx; }
            }
        }
    }

    __syncthreads();
#pragma unroll
    for (int i = 0; i < 4; i++) {
        redv[tm * 4 + i][tk] = bestv[i];
        redi[tm * 4 + i][tk] = besti[i];
    }
    __syncthreads();
    if (tid < 64) {
        float bv = redv[tid][0];
        int   bi = redi[tid][0];
#pragma unroll
        for (int t = 1; t < 16; t++) {
            float v = redv[tid][t];
            int   ix = redi[tid][t];
            if (v < bv || (v == bv && ix < bi)) { bv = v; bi = ix; }
        }
        g_best[rowid[tid]] = bi;
    }
}

// ---------------------------------------------------------------------------
// Kernel 3: gather + mask + loss accumulation. One warp per position.
// Mask read as 32-bit words (nonzero == true): works for int32 or float32.
// ---------------------------------------------------------------------------
__global__ void __launch_bounds__(256) quant_kernel(
    const float* __restrict__ z, const unsigned int* __restrict__ mask,
    const float* __restrict__ cb, float* __restrict__ outq,
    float* __restrict__ outi)
{
    __shared__ float wsum[8];
    const int warp = threadIdx.x >> 5;
    const int lane = threadIdx.x & 31;
    const int pos  = blockIdx.x * 8 + warp;

    const int idx = g_best[pos];
    const bool mk = (mask[pos] != 0u);
    const float m = mk ? 1.f : 0.f;
    const float4* zp = (const float4*)(z  + (size_t)pos * DD);
    const float4* ep = (const float4*)(cb + (size_t)idx * DD);
    float4* op = (float4*)(outq + (size_t)pos * DD);

    float s = 0.f;
#pragma unroll
    for (int i = lane; i < DD / 4; i += 32) {
        float4 zv = zp[i];
        float4 ev = ep[i];
        float dx = ev.x - zv.x, dy = ev.y - zv.y,
              dz = ev.z - zv.z, dw = ev.w - zv.w;
        s += dx * dx + dy * dy + dz * dz + dw * dw;
        op[i] = make_float4(ev.x * m, ev.y * m, ev.z * m, ev.w * m);
    }
    if (lane == 0) outi[pos] = mk ? (float)idx : -1.0f;

#pragma unroll
    for (int off = 16; off > 0; off >>= 1)
        s += __shfl_down_sync(0xFFFFFFFFu, s, off);
    if (lane == 0) wsum[warp] = s;
    __syncthreads();
    if (threadIdx.x == 0) {
        float b = 0.f;
#pragma unroll
        for (int w = 0; w < 8; w++) b += wsum[w];
        atomicAdd(&g_loss, (double)b);
    }
}

// ---------------------------------------------------------------------------
// Kernel 4: finalize commit loss.
// ---------------------------------------------------------------------------
__global__ void finalize_kernel(float* __restrict__ out_loss) {
    out_loss[0] = (float)(COMMIT_W * g_loss / ((double)MM * (double)DD));
}

// ---------------------------------------------------------------------------
extern "C" void kernel_launch(void* const* d_in, const int* in_sizes, int n_in,
                              void* d_out, int out_size) {
    const float*        z    = (const float*)d_in[0];
    const unsigned int* mask = (const unsigned int*)d_in[1];
    const float*        cb   = (const float*)d_in[2];

    float* outq = (float*)d_out;                         // (B,N,D)
    float* outi = outq + (size_t)MM * DD;                // (B,N) indices as float
    float* outl = outi + MM;                             // scalar loss

    prep_kernel<<<1, 512>>>(cb);
    screen_kernel<<<MM / 128, 256>>>(z, cb);
    rescore_kernel<<<MM / 64, 256>>>(z, cb);
    quant_kernel<<<MM / 8, 256>>>(z, mask, cb, outq, outi);
    finalize_kernel<<<1, 1>>>(outl);
}